// round 12
// baseline (speedup 1.0000x reference)
#include <cuda_runtime.h>
#include <cuda_fp16.h>
#include <cstdint>

#define Bc   16
#define Nc   10000
#define TOKc (Bc * Nc)          // 160000
#define EPSc 1e-5f

#define XROWB 272               // padded fp16 row (128 cols = 256B + 16 pad)
#define W_OFF 34816             // X region size (128 rows * 272)
#define WSETB 34816             // one full W set, same padded layout
#define SMEMB 104448            // X + 2 W buffers

// ---------------- scratch (no allocations allowed) ----------------
__device__ __half g_A[(size_t)TOKc * 128];
__device__ __half g_C[(size_t)TOKc * 128];
__device__ __half g_P[(size_t)TOKc * 128];
__device__ __align__(16) __half g_wimg[6 * 16384];   // 6 matrices (W^T), fp16
__device__ int   g_tour[TOKc];
__device__ int   g_is64;

__device__ __forceinline__ float silu_f(float x) { return x / (1.f + __expf(-x)); }

__device__ __forceinline__ uint32_t smem_u32(const void* p) {
    uint32_t a;
    asm("{ .reg .u64 tmp; cvta.to.shared.u64 tmp, %1; cvt.u32.u64 %0, tmp; }" : "=r"(a) : "l"(p));
    return a;
}
__device__ __forceinline__ void ldsm4(uint32_t (&r)[4], uint32_t addr) {
    asm volatile("ldmatrix.sync.aligned.m8n8.x4.shared.b16 {%0,%1,%2,%3}, [%4];"
        : "=r"(r[0]), "=r"(r[1]), "=r"(r[2]), "=r"(r[3]) : "r"(addr));
}
__device__ __forceinline__ void mma16816h(float (&d)[4], const uint32_t (&a)[4], uint32_t b0, uint32_t b1) {
    asm volatile("mma.sync.aligned.m16n8k16.row.col.f32.f16.f16.f32 "
        "{%0,%1,%2,%3}, {%4,%5,%6,%7}, {%8,%9}, {%0,%1,%2,%3};"
        : "+f"(d[0]), "+f"(d[1]), "+f"(d[2]), "+f"(d[3])
        : "r"(a[0]), "r"(a[1]), "r"(a[2]), "r"(a[3]), "r"(b0), "r"(b1));
}
__device__ __forceinline__ uint32_t pack2h(float f0, float f1) {
    __half2 h = __floats2half2_rn(f0, f1);
    return *(uint32_t*)&h;
}
#define CPWAIT0() asm volatile("cp.async.wait_group 0;" ::: "memory")

// ---- tour dtype detection ----
__global__ void k_detect(const int* __restrict__ tour_raw) {
    int allzero = 1;
    for (int i = 1; i < 129; i += 2) allzero &= (tour_raw[i] == 0);
    g_is64 = allzero;
}
__global__ void k_convert(const int* __restrict__ tour_raw, int* __restrict__ tour) {
    int t = blockIdx.x * blockDim.x + threadIdx.x;
    if (t >= TOKc) return;
    tour[t] = g_is64 ? tour_raw[2 * t] : tour_raw[t];
}

// ---- prep: W^T fp16.  img[m*16384 + n*128 + k] ----
__global__ void k_prepw(const float* __restrict__ W1m, const float* __restrict__ W2m,
                        const float* __restrict__ W1u, const float* __restrict__ W2u,
                        __half* __restrict__ img) {
    int idx = blockIdx.x * 256 + threadIdx.x;
    if (idx >= 6 * 16384) return;
    int m = idx >> 14, e = idx & 16383;
    int n = e >> 7, k = e & 127;
    const float* src;
    switch (m) {
        case 0: src = W1m; break;
        case 1: src = W1m + 16384; break;
        case 2: src = W2m; break;
        case 3: src = W1u; break;
        case 4: src = W1u + 16384; break;
        default: src = W2u; break;
    }
    img[(size_t)m * 16384 + n * 128 + k] = __float2half_rn(src[k * 128 + n]);
}

// ---- async full W set (32 KB) -> stage buffer, one commit group ----
__device__ __forceinline__ void issue_w_full(char* sdyn, const __half* Wi, int stage, int tid) {
#pragma unroll
    for (int it = 0; it < 8; it++) {
        int i = tid + it * 256;          // 0..2047 segments of 16B
        int r = i >> 4, seg = i & 15;
        const char* src = (const char*)Wi + r * 256 + seg * 16;
        uint32_t dst = smem_u32(sdyn + W_OFF + stage * WSETB + r * XROWB + seg * 16);
        asm volatile("cp.async.cg.shared.global [%0], [%1], 16;" :: "r"(dst), "l"(src));
    }
    asm volatile("cp.async.commit_group;" ::: "memory");
}

// ---- pack 64 fp32 into fp16 X smem at (row, half) ----
__device__ __forceinline__ void pack_store_x64(char* sdyn, int row, int half_, const float* v) {
    uint32_t hx[32];
#pragma unroll
    for (int j = 0; j < 32; j++) hx[j] = pack2h(v[2 * j], v[2 * j + 1]);
    char* px = sdyn + row * XROWB + half_ * 128;
#pragma unroll
    for (int j = 0; j < 8; j++) *(uint4*)(px + j * 16) = ((const uint4*)hx)[j];
}

// ---- warp 64x32 full-K mainloop (X + W resident, no barriers) ----
__device__ __forceinline__ void mainloop_set(uint32_t sb, int lane, int mbase, int nbase,
                                             int stage, float (&acc)[4][4][4]) {
#pragma unroll
    for (int mf = 0; mf < 4; mf++)
#pragma unroll
        for (int nf = 0; nf < 4; nf++)
#pragma unroll
            for (int e = 0; e < 4; e++) acc[mf][nf][e] = 0.f;
    const uint32_t aB = sb + (mbase + (lane & 15)) * XROWB + ((lane >> 4) << 4);
    const int g = lane >> 3;
    const uint32_t bB = sb + W_OFF + stage * WSETB
                      + (nbase + ((g >> 1) << 3) + (lane & 7)) * XROWB + (g & 1) * 16;
#pragma unroll
    for (int ks = 0; ks < 8; ks++) {
        const int kb = ks * 32;
        uint32_t bh[2][4];
        ldsm4(bh[0], bB + kb);
        ldsm4(bh[1], bB + 16 * XROWB + kb);
#pragma unroll
        for (int mf = 0; mf < 4; mf++) {
            uint32_t ah[4];
            ldsm4(ah, aB + mf * 16 * XROWB + kb);
#pragma unroll
            for (int nf = 0; nf < 4; nf++)
                mma16816h(acc[mf][nf], ah, bh[nf >> 1][(nf & 1) * 2], bh[nf >> 1][(nf & 1) * 2 + 1]);
        }
    }
}

// ================= K_A: gather h -> X; 3 GEMM sets -> A, C, P (fp16) =================
__global__ void __launch_bounds__(256, 2)
k_mma3(const float* __restrict__ h, const int* __restrict__ tour,
       const __half* __restrict__ I0, const __half* __restrict__ I1,
       const __half* __restrict__ I2,
       __half* __restrict__ oA, __half* __restrict__ oC, __half* __restrict__ oP) {
    extern __shared__ char sdyn[];
    const int tid = threadIdx.x, lane = tid & 31, wid = tid >> 5;
    const int m0 = blockIdx.x * 128;

    issue_w_full(sdyn, I0, 0, tid);
    {   // gather prologue: thread owns half a token row
        const int row = tid >> 1, half_ = tid & 1;
        const int t = m0 + row;
        int b = t / Nc;
        int node = tour[t];
        const float* src = h + ((size_t)b * Nc + node) * 128 + half_ * 64;
        float v[64];
#pragma unroll
        for (int j = 0; j < 16; j++) *(float4*)&v[j * 4] = *(const float4*)&src[j * 4];
        pack_store_x64(sdyn, row, half_, v);
    }
    CPWAIT0();
    __syncthreads();

    const int mbase = (wid & 1) * 64, nbase = (wid >> 1) * 32;
    const uint32_t sb = smem_u32(sdyn);
    const __half* imgs[3] = {I0, I1, I2};

#pragma unroll 1
    for (int set = 0; set < 3; set++) {
        if (set < 2) issue_w_full(sdyn, imgs[set + 1], (set + 1) & 1, tid);
        float acc[4][4][4];
        mainloop_set(sb, lane, mbase, nbase, set & 1, acc);
        __half* o = (set == 0) ? oA : (set == 1 ? oC : oP);
#pragma unroll
        for (int mf = 0; mf < 4; mf++)
#pragma unroll
            for (int nf = 0; nf < 4; nf++) {
                int rr = (lane >> 2) + mf * 16;
                size_t row = m0 + mbase + rr;
                int col = nbase + (lane & 3) * 2 + nf * 8;
                *(uint32_t*)&o[row * 128 + col]       = pack2h(acc[mf][nf][0], acc[mf][nf][1]);
                *(uint32_t*)&o[(row + 8) * 128 + col] = pack2h(acc[mf][nf][2], acc[mf][nf][3]);
            }
        if (set < 2) {
            CPWAIT0();
            __syncthreads();
        }
    }
}

// ===== K_B: roll -> W2m -> W1u1(silu+P) -> W2u -> LN+scatter =====
__global__ void __launch_bounds__(256, 2)
k_chain(const __half* __restrict__ A, const __half* __restrict__ Cb,
        const __half* __restrict__ P, const float* __restrict__ h,
        const int* __restrict__ tour,
        const __half* __restrict__ Im, const __half* __restrict__ Iu,
        const __half* __restrict__ Io,
        const float* __restrict__ b1m, const float* __restrict__ b2m,
        const float* __restrict__ b1u, const float* __restrict__ b2u,
        const float* __restrict__ gamma, const float* __restrict__ beta,
        float* __restrict__ out) {
    extern __shared__ char sdyn[];
    const int tid = threadIdx.x, lane = tid & 31, wid = tid >> 5;
    const int m0 = blockIdx.x * 128;

    issue_w_full(sdyn, Im, 0, tid);
    {   // roll prologue: ys = silu(A + C[i-1] + b1m) + silu(A + C[i+1] + b1m)
        const int row = tid >> 1, half_ = tid & 1;
        const int t = m0 + row;
        int b = t / Nc, i = t - b * Nc;
        int tp = (i == 0)      ? t + Nc - 1 : t - 1;
        int tx = (i == Nc - 1) ? t - Nc + 1 : t + 1;
        const int cb = half_ * 64;
        const __half2* Ar = (const __half2*)A  + (size_t)t  * 64 + half_ * 32;
        const __half2* Cp = (const __half2*)Cb + (size_t)tp * 64 + half_ * 32;
        const __half2* Cn = (const __half2*)Cb + (size_t)tx * 64 + half_ * 32;
        float v[64];
#pragma unroll
        for (int j = 0; j < 32; j++) {
            float2 a  = __half22float2(Ar[j]);
            float2 cp = __half22float2(Cp[j]);
            float2 cn = __half22float2(Cn[j]);
            float2 bb = *(const float2*)&b1m[cb + 2 * j];
            v[2 * j + 0] = silu_f(a.x + cp.x + bb.x) + silu_f(a.x + cn.x + bb.x);
            v[2 * j + 1] = silu_f(a.y + cp.y + bb.y) + silu_f(a.y + cn.y + bb.y);
        }
        pack_store_x64(sdyn, row, half_, v);
    }
    CPWAIT0();
    __syncthreads();

    const int mbase = (wid & 1) * 64, nbase = (wid >> 1) * 32;
    const uint32_t sb = smem_u32(sdyn);
    const __half* imgs[3] = {Im, Iu, Io};

#pragma unroll 1
    for (int set = 0; set < 3; set++) {
        if (set < 2) issue_w_full(sdyn, imgs[set + 1], (set + 1) & 1, tid);
        float acc[4][4][4];
        mainloop_set(sb, lane, mbase, nbase, set & 1, acc);
        __syncthreads();                    // all warps done reading X before rewrite
        if (set == 0) {          // msg = acc + 2*b2m -> X (fp16)
#pragma unroll
            for (int mf = 0; mf < 4; mf++)
#pragma unroll
                for (int nf = 0; nf < 4; nf++) {
                    int rr = (lane >> 2) + mf * 16;
                    int col = nbase + (lane & 3) * 2 + nf * 8;
                    float2 b2 = *(const float2*)&b2m[col];
#pragma unroll
                    for (int hf = 0; hf < 2; hf++) {
                        int r = mbase + rr + hf * 8;
                        *(uint32_t*)(sdyn + r * XROWB + col * 2) =
                            pack2h(acc[mf][nf][hf * 2 + 0] + 2.f * b2.x,
                                   acc[mf][nf][hf * 2 + 1] + 2.f * b2.y);
                    }
                }
        } else if (set == 1) {   // t = silu(acc + P + b1u) -> X (fp16)
#pragma unroll
            for (int mf = 0; mf < 4; mf++)
#pragma unroll
                for (int nf = 0; nf < 4; nf++) {
                    int rr = (lane >> 2) + mf * 16;
                    int col = nbase + (lane & 3) * 2 + nf * 8;
                    float2 bu = *(const float2*)&b1u[col];
#pragma unroll
                    for (int hf = 0; hf < 2; hf++) {
                        int r = mbase + rr + hf * 8;
                        size_t grow = m0 + r;
                        float2 pv = __half22float2(*(const __half2*)&P[grow * 128 + col]);
                        *(uint32_t*)(sdyn + r * XROWB + col * 2) =
                            pack2h(silu_f(acc[mf][nf][hf * 2 + 0] + pv.x + bu.x),
                                   silu_f(acc[mf][nf][hf * 2 + 1] + pv.y + bu.y));
                    }
                }
        } else {                 // LN + scatter
            uint32_t* S = (uint32_t*)sdyn;   // fp16 pair staging over X region (dead), stride 66
#pragma unroll
            for (int mf = 0; mf < 4; mf++)
#pragma unroll
                for (int nf = 0; nf < 4; nf++) {
                    int rr = mbase + (lane >> 2) + mf * 16;
                    int cp2 = (nbase + (lane & 3) * 2 + nf * 8) >> 1;
                    S[rr * 66 + cp2]       = pack2h(acc[mf][nf][0], acc[mf][nf][1]);
                    S[(rr + 8) * 66 + cp2] = pack2h(acc[mf][nf][2], acc[mf][nf][3]);
                }
            __syncthreads();
            const int row = tid >> 1, half_ = tid & 1;
            const int t = m0 + row;
            const int cb = half_ * 64;
            int b = t / Nc;
            int node = tour[t];
            const float* hrow = h + ((size_t)b * Nc + node) * 128 + cb;
            float v[64];
            float s = 0.f, ss = 0.f;
#pragma unroll
            for (int j = 0; j < 32; j++) {
                uint32_t pw = S[row * 66 + half_ * 32 + j];
                float2 a2 = __half22float2(*(const __half2*)&pw);
                float2 h2 = *(const float2*)&hrow[2 * j];
                float2 b4 = *(const float2*)&b2u[cb + 2 * j];
                v[2 * j + 0] = a2.x + h2.x + b4.x;
                v[2 * j + 1] = a2.y + h2.y + b4.y;
                s += v[2 * j] + v[2 * j + 1];
                ss += v[2 * j] * v[2 * j] + v[2 * j + 1] * v[2 * j + 1];
            }
            s  += __shfl_xor_sync(0xFFFFFFFFu, s, 1);
            ss += __shfl_xor_sync(0xFFFFFFFFu, ss, 1);
            float mu = s * (1.f / 128.f);
            float var = ss * (1.f / 128.f) - mu * mu;
            float inv = rsqrtf(var + EPSc);
            size_t base = ((size_t)b * Nc + node) * 128 + cb;
#pragma unroll
            for (int j = 0; j < 16; j++) {
                float4 g4 = *(const float4*)&gamma[cb + j * 4];
                float4 z4 = *(const float4*)&beta[cb + j * 4];
                *(float4*)&out[base + j * 4] = make_float4(
                    (v[j * 4 + 0] - mu) * inv * g4.x + z4.x,
                    (v[j * 4 + 1] - mu) * inv * g4.y + z4.y,
                    (v[j * 4 + 2] - mu) * inv * g4.z + z4.z,
                    (v[j * 4 + 3] - mu) * inv * g4.w + z4.w);
            }
        }
        if (set < 2) {
            CPWAIT0();
            __syncthreads();
        }
    }
}

extern "C" void kernel_launch(void* const* d_in, const int* in_sizes, int n_in,
                              void* d_out, int out_size) {
    const float* h        = (const float*)d_in[0];
    const int*   tour_raw = (const int*)d_in[1];
    const float* W1m      = (const float*)d_in[2];
    const float* b1m      = (const float*)d_in[3];
    const float* W2m      = (const float*)d_in[4];
    const float* b2m      = (const float*)d_in[5];
    const float* W1u      = (const float*)d_in[6];
    const float* b1u      = (const float*)d_in[7];
    const float* W2u      = (const float*)d_in[8];
    const float* b2u      = (const float*)d_in[9];
    const float* gamma    = (const float*)d_in[10];
    const float* beta     = (const float*)d_in[11];
    float* out            = (float*)d_out;

    __half *A, *C, *P, *wimg;
    int* tour;
    cudaGetSymbolAddress((void**)&A,    g_A);
    cudaGetSymbolAddress((void**)&C,    g_C);
    cudaGetSymbolAddress((void**)&P,    g_P);
    cudaGetSymbolAddress((void**)&wimg, g_wimg);
    cudaGetSymbolAddress((void**)&tour, g_tour);

    cudaFuncSetAttribute(k_mma3,  cudaFuncAttributeMaxDynamicSharedMemorySize, SMEMB);
    cudaFuncSetAttribute(k_chain, cudaFuncAttributeMaxDynamicSharedMemorySize, SMEMB);

    // weight images: 0=W1m0 1=W1m1 2=W2m 3=W1u0 4=W1u1 5=W2u (each 16384 fp16)
    __half* I0 = wimg;
    __half* I1 = wimg + 16384;
    __half* I2 = wimg + 2 * 16384;
    __half* I3 = wimg + 3 * 16384;
    __half* I4 = wimg + 4 * 16384;
    __half* I5 = wimg + 5 * 16384;

    const int G = TOKc / 128;   // 1250 blocks

    k_detect<<<1, 1>>>(tour_raw);
    k_convert<<<(TOKc + 255) / 256, 256>>>(tour_raw, tour);
    k_prepw<<<(6 * 16384 + 255) / 256, 256>>>(W1m, W2m, W1u, W2u, wimg);

    // K_A: A = gather(h)@W1m0, C = @W1m1, P = @W1u0
    k_mma3<<<G, 256, SMEMB>>>(h, tour, I0, I1, I3, A, C, P);
    // K_B: roll -> W2m -> W1u1(silu+P) -> W2u -> LN -> scatter
    k_chain<<<G, 256, SMEMB>>>(A, C, P, h, tour, I2, I4, I5,
                               b1m, b2m, b1u, b2u, gamma, beta, out);
}

// round 14
// speedup vs baseline: 1.1750x; 1.1750x over previous
#include <cuda_runtime.h>
#include <cuda_fp16.h>
#include <cstdint>

#define Bc   16
#define Nc   10000
#define TOKc (Bc * Nc)          // 160000
#define EPSc 1e-5f

#define XROWB    272            // padded fp16 X row (128 cols = 256B + 16 pad)
#define WBUF_OFF 34816          // X region size (128 rows * 272)
#define WSTG     6144           // W chunk stage: 128 rows * 48B
#define WROWB    48             // 32B data + 16 pad (conflict-free ldsm)
#define NSTAGE   4
#define SMEMB    (34816 + NSTAGE * WSTG)   // 59392

// ---------------- scratch (no allocations allowed) ----------------
__device__ __half g_A[(size_t)TOKc * 128];
__device__ __half g_C[(size_t)TOKc * 128];
__device__ __half g_P[(size_t)TOKc * 128];
__device__ __align__(16) __half g_wimg[6 * 16384];   // 6 matrices (W^T), fp16
__device__ int   g_tour[TOKc];
__device__ int   g_is64;

__device__ __forceinline__ float silu_f(float x) { return x / (1.f + __expf(-x)); }

__device__ __forceinline__ uint32_t smem_u32(const void* p) {
    uint32_t a;
    asm("{ .reg .u64 tmp; cvta.to.shared.u64 tmp, %1; cvt.u32.u64 %0, tmp; }" : "=r"(a) : "l"(p));
    return a;
}
__device__ __forceinline__ void ldsm4(uint32_t (&r)[4], uint32_t addr) {
    asm volatile("ldmatrix.sync.aligned.m8n8.x4.shared.b16 {%0,%1,%2,%3}, [%4];"
        : "=r"(r[0]), "=r"(r[1]), "=r"(r[2]), "=r"(r[3]) : "r"(addr));
}
__device__ __forceinline__ void mma16816h(float (&d)[4], const uint32_t (&a)[4], uint32_t b0, uint32_t b1) {
    asm volatile("mma.sync.aligned.m16n8k16.row.col.f32.f16.f16.f32 "
        "{%0,%1,%2,%3}, {%4,%5,%6,%7}, {%8,%9}, {%0,%1,%2,%3};"
        : "+f"(d[0]), "+f"(d[1]), "+f"(d[2]), "+f"(d[3])
        : "r"(a[0]), "r"(a[1]), "r"(a[2]), "r"(a[3]), "r"(b0), "r"(b1));
}
__device__ __forceinline__ uint32_t pack2h(float f0, float f1) {
    __half2 h = __floats2half2_rn(f0, f1);
    return *(uint32_t*)&h;
}
#define CPWAIT1() asm volatile("cp.async.wait_group 1;" ::: "memory")

// ---- tour dtype detection ----
__global__ void k_detect(const int* __restrict__ tour_raw) {
    int allzero = 1;
    for (int i = 1; i < 129; i += 2) allzero &= (tour_raw[i] == 0);
    g_is64 = allzero;
}
__global__ void k_convert(const int* __restrict__ tour_raw, int* __restrict__ tour) {
    int t = blockIdx.x * blockDim.x + threadIdx.x;
    if (t >= TOKc) return;
    tour[t] = g_is64 ? tour_raw[2 * t] : tour_raw[t];
}

// ---- prep: W^T fp16.  img[m*16384 + n*128 + k] ----
__global__ void k_prepw(const float* __restrict__ W1m, const float* __restrict__ W2m,
                        const float* __restrict__ W1u, const float* __restrict__ W2u,
                        __half* __restrict__ img) {
    int idx = blockIdx.x * 256 + threadIdx.x;
    if (idx >= 6 * 16384) return;
    int m = idx >> 14, e = idx & 16383;
    int n = e >> 7, k = e & 127;
    const float* src;
    switch (m) {
        case 0: src = W1m; break;
        case 1: src = W1m + 16384; break;
        case 2: src = W2m; break;
        case 3: src = W1u; break;
        case 4: src = W1u + 16384; break;
        default: src = W2u; break;
    }
    img[(size_t)m * 16384 + n * 128 + k] = __float2half_rn(src[k * 128 + n]);
}

// ---- async W chunk: 128 n-rows x 16 k (32B) -> stage ----
__device__ __forceinline__ void issue_w_chunk(char* sdyn, const __half* Wi,
                                              int kc, int stage, int tid) {
    int r = tid >> 1, seg = tid & 1;
    const char* src = (const char*)Wi + r * 256 + kc * 32 + seg * 16;
    uint32_t dst = smem_u32(sdyn + WBUF_OFF + stage * WSTG + r * WROWB + seg * 16);
    asm volatile("cp.async.cg.shared.global [%0], [%1], 16;" :: "r"(dst), "l"(src));
    asm volatile("cp.async.commit_group;" ::: "memory");
}

// ---- pack 64 fp32 into fp16 X smem at (row, half) ----
__device__ __forceinline__ void pack_store_x64(char* sdyn, int row, int half_, const float* v) {
    uint32_t hx[32];
#pragma unroll
    for (int j = 0; j < 32; j++) hx[j] = pack2h(v[2 * j], v[2 * j + 1]);
    char* px = sdyn + row * XROWB + half_ * 128;
#pragma unroll
    for (int j = 0; j < 8; j++) *(uint4*)(px + j * 16) = ((const uint4*)hx)[j];
}

// ---- warp 64x32 chunk step (one 16-k slice), single-term fp16 ----
__device__ __forceinline__ void mainloop_chunk(uint32_t sb, int lane, int mbase, int nbase,
                                               int stage, int kb, float (&acc)[4][4][4]) {
    const uint32_t aBase = sb + (mbase + (lane & 15)) * XROWB + ((lane >> 4) << 4) + kb;
    const int g = lane >> 3;
    const uint32_t bBase = sb + WBUF_OFF + stage * WSTG
                         + (nbase + ((g >> 1) << 3) + (lane & 7)) * WROWB + (g & 1) * 16;
    uint32_t bh[2][4];
    ldsm4(bh[0], bBase);
    ldsm4(bh[1], bBase + 16 * WROWB);
#pragma unroll
    for (int mf = 0; mf < 4; mf++) {
        uint32_t ah[4];
        ldsm4(ah, aBase + mf * 16 * XROWB);
#pragma unroll
        for (int nf = 0; nf < 4; nf++) {
            mma16816h(acc[mf][nf], ah, bh[nf >> 1][(nf & 1) * 2], bh[nf >> 1][(nf & 1) * 2 + 1]);
        }
    }
}

// ================= K_A: gather h -> X; 3 streamed GEMM sets -> A, C, P (fp16) =================
__global__ void __launch_bounds__(256, 2)
k_mma3(const float* __restrict__ h, const int* __restrict__ tour,
       const __half* __restrict__ I0, const __half* __restrict__ I1,
       const __half* __restrict__ I2,
       __half* __restrict__ oA, __half* __restrict__ oC, __half* __restrict__ oP) {
    extern __shared__ char sdyn[];
    const int tid = threadIdx.x, lane = tid & 31, wid = tid >> 5;
    const int m0 = blockIdx.x * 128;

    issue_w_chunk(sdyn, I0, 0, 0, tid);
    issue_w_chunk(sdyn, I0, 1, 1, tid);
    {   // gather prologue: thread owns half a token row
        const int row = tid >> 1, half_ = tid & 1;
        const int t = m0 + row;
        int b = t / Nc;
        int node = tour[t];
        const float* src = h + ((size_t)b * Nc + node) * 128 + half_ * 64;
        float v[64];
#pragma unroll
        for (int j = 0; j < 16; j++) *(float4*)&v[j * 4] = *(const float4*)&src[j * 4];
        pack_store_x64(sdyn, row, half_, v);
    }

    const int mbase = (wid & 1) * 64, nbase = (wid >> 1) * 32;
    const uint32_t sb = smem_u32(sdyn);

#pragma unroll 1
    for (int set = 0; set < 3; set++) {
        float acc[4][4][4];
#pragma unroll
        for (int mf = 0; mf < 4; mf++)
#pragma unroll
            for (int nf = 0; nf < 4; nf++)
#pragma unroll
                for (int e = 0; e < 4; e++) acc[mf][nf][e] = 0.f;
#pragma unroll 1
        for (int ks = 0; ks < 8; ks++) {
            const int gc = set * 8 + ks;
            CPWAIT1();
            __syncthreads();
            const int ngc = gc + 2;
            if (ngc < 24) {
                const __half* nimg = (ngc < 8) ? I0 : (ngc < 16 ? I1 : I2);
                issue_w_chunk(sdyn, nimg, ngc & 7, ngc & 3, tid);
            }
            mainloop_chunk(sb, lane, mbase, nbase, gc & 3, ks * 32, acc);
        }
        __half* o = (set == 0) ? oA : (set == 1 ? oC : oP);
#pragma unroll
        for (int mf = 0; mf < 4; mf++)
#pragma unroll
            for (int nf = 0; nf < 4; nf++) {
                int rr = (lane >> 2) + mf * 16;
                size_t row = m0 + mbase + rr;
                int col = nbase + (lane & 3) * 2 + nf * 8;
                *(uint32_t*)&o[row * 128 + col]       = pack2h(acc[mf][nf][0], acc[mf][nf][1]);
                *(uint32_t*)&o[(row + 8) * 128 + col] = pack2h(acc[mf][nf][2], acc[mf][nf][3]);
            }
    }
}

// ===== K_B: roll -> W2m -> W1u1(silu+P) -> W2u -> LN+scatter (streamed W, fp16 MMA) =====
__global__ void __launch_bounds__(256, 2)
k_chain(const __half* __restrict__ A, const __half* __restrict__ Cb,
        const __half* __restrict__ P, const float* __restrict__ h,
        const int* __restrict__ tour,
        const __half* __restrict__ Im, const __half* __restrict__ Iu,
        const __half* __restrict__ Io,
        const float* __restrict__ b1m, const float* __restrict__ b2m,
        const float* __restrict__ b1u, const float* __restrict__ b2u,
        const float* __restrict__ gamma, const float* __restrict__ beta,
        float* __restrict__ out) {
    extern __shared__ char sdyn[];
    const int tid = threadIdx.x, lane = tid & 31, wid = tid >> 5;
    const int m0 = blockIdx.x * 128;

    issue_w_chunk(sdyn, Im, 0, 0, tid);
    issue_w_chunk(sdyn, Im, 1, 1, tid);
    {   // roll prologue: ys = silu(A + C[i-1] + b1m) + silu(A + C[i+1] + b1m)
        const int row = tid >> 1, half_ = tid & 1;
        const int t = m0 + row;
        int b = t / Nc, i = t - b * Nc;
        int tp = (i == 0)      ? t + Nc - 1 : t - 1;
        int tx = (i == Nc - 1) ? t - Nc + 1 : t + 1;
        const int cb = half_ * 64;
        const __half2* Ar = (const __half2*)A  + (size_t)t  * 64 + half_ * 32;
        const __half2* Cp = (const __half2*)Cb + (size_t)tp * 64 + half_ * 32;
        const __half2* Cn = (const __half2*)Cb + (size_t)tx * 64 + half_ * 32;
        float v[64];
#pragma unroll
        for (int j = 0; j < 32; j++) {
            float2 a  = __half22float2(Ar[j]);
            float2 cp = __half22float2(Cp[j]);
            float2 cn = __half22float2(Cn[j]);
            float2 bb = *(const float2*)&b1m[cb + 2 * j];
            v[2 * j + 0] = silu_f(a.x + cp.x + bb.x) + silu_f(a.x + cn.x + bb.x);
            v[2 * j + 1] = silu_f(a.y + cp.y + bb.y) + silu_f(a.y + cn.y + bb.y);
        }
        pack_store_x64(sdyn, row, half_, v);
    }

    const int mbase = (wid & 1) * 64, nbase = (wid >> 1) * 32;
    const uint32_t sb = smem_u32(sdyn);

#pragma unroll 1
    for (int set = 0; set < 3; set++) {
        float acc[4][4][4];
#pragma unroll
        for (int mf = 0; mf < 4; mf++)
#pragma unroll
            for (int nf = 0; nf < 4; nf++)
#pragma unroll
                for (int e = 0; e < 4; e++) acc[mf][nf][e] = 0.f;
#pragma unroll 1
        for (int ks = 0; ks < 8; ks++) {
            const int gc = set * 8 + ks;
            CPWAIT1();
            __syncthreads();
            const int ngc = gc + 2;
            if (ngc < 24) {
                const __half* nimg = (ngc < 8) ? Im : (ngc < 16 ? Iu : Io);
                issue_w_chunk(sdyn, nimg, ngc & 7, ngc & 3, tid);
            }
            mainloop_chunk(sb, lane, mbase, nbase, gc & 3, ks * 32, acc);
        }
        __syncthreads();                    // all warps done reading X before rewrite
        if (set == 0) {          // msg = acc + 2*b2m -> X (fp16)
#pragma unroll
            for (int mf = 0; mf < 4; mf++)
#pragma unroll
                for (int nf = 0; nf < 4; nf++) {
                    int rr = (lane >> 2) + mf * 16;
                    int col = nbase + (lane & 3) * 2 + nf * 8;
                    float2 b2 = *(const float2*)&b2m[col];
#pragma unroll
                    for (int hf = 0; hf < 2; hf++) {
                        int r = mbase + rr + hf * 8;
                        *(uint32_t*)(sdyn + r * XROWB + col * 2) =
                            pack2h(acc[mf][nf][hf * 2 + 0] + 2.f * b2.x,
                                   acc[mf][nf][hf * 2 + 1] + 2.f * b2.y);
                    }
                }
        } else if (set == 1) {   // t = silu(acc + P + b1u) -> X (fp16)
#pragma unroll
            for (int mf = 0; mf < 4; mf++)
#pragma unroll
                for (int nf = 0; nf < 4; nf++) {
                    int rr = (lane >> 2) + mf * 16;
                    int col = nbase + (lane & 3) * 2 + nf * 8;
                    float2 bu = *(const float2*)&b1u[col];
#pragma unroll
                    for (int hf = 0; hf < 2; hf++) {
                        int r = mbase + rr + hf * 8;
                        size_t grow = m0 + r;
                        float2 pv = __half22float2(*(const __half2*)&P[grow * 128 + col]);
                        *(uint32_t*)(sdyn + r * XROWB + col * 2) =
                            pack2h(silu_f(acc[mf][nf][hf * 2 + 0] + pv.x + bu.x),
                                   silu_f(acc[mf][nf][hf * 2 + 1] + pv.y + bu.y));
                    }
                }
        } else {                 // LN + scatter
            uint32_t* S = (uint32_t*)sdyn;   // fp16 pair staging over X region (dead), stride 66
#pragma unroll
            for (int mf = 0; mf < 4; mf++)
#pragma unroll
                for (int nf = 0; nf < 4; nf++) {
                    int rr = mbase + (lane >> 2) + mf * 16;
                    int cp2 = (nbase + (lane & 3) * 2 + nf * 8) >> 1;
                    S[rr * 66 + cp2]       = pack2h(acc[mf][nf][0], acc[mf][nf][1]);
                    S[(rr + 8) * 66 + cp2] = pack2h(acc[mf][nf][2], acc[mf][nf][3]);
                }
            __syncthreads();
            const int row = tid >> 1, half_ = tid & 1;
            const int t = m0 + row;
            const int cb = half_ * 64;
            int b = t / Nc;
            int node = tour[t];
            const float* hrow = h + ((size_t)b * Nc + node) * 128 + cb;
            float v[64];
            float s = 0.f, ss = 0.f;
#pragma unroll
            for (int j = 0; j < 32; j++) {
                uint32_t pw = S[row * 66 + half_ * 32 + j];
                float2 a2 = __half22float2(*(const __half2*)&pw);
                float2 h2 = *(const float2*)&hrow[2 * j];
                float2 b4 = *(const float2*)&b2u[cb + 2 * j];
                v[2 * j + 0] = a2.x + h2.x + b4.x;
                v[2 * j + 1] = a2.y + h2.y + b4.y;
                s += v[2 * j] + v[2 * j + 1];
                ss += v[2 * j] * v[2 * j] + v[2 * j + 1] * v[2 * j + 1];
            }
            s  += __shfl_xor_sync(0xFFFFFFFFu, s, 1);
            ss += __shfl_xor_sync(0xFFFFFFFFu, ss, 1);
            float mu = s * (1.f / 128.f);
            float var = ss * (1.f / 128.f) - mu * mu;
            float inv = rsqrtf(var + EPSc);
            size_t base = ((size_t)b * Nc + node) * 128 + cb;
#pragma unroll
            for (int j = 0; j < 16; j++) {
                float4 g4 = *(const float4*)&gamma[cb + j * 4];
                float4 z4 = *(const float4*)&beta[cb + j * 4];
                *(float4*)&out[base + j * 4] = make_float4(
                    (v[j * 4 + 0] - mu) * inv * g4.x + z4.x,
                    (v[j * 4 + 1] - mu) * inv * g4.y + z4.y,
                    (v[j * 4 + 2] - mu) * inv * g4.z + z4.z,
                    (v[j * 4 + 3] - mu) * inv * g4.w + z4.w);
            }
        }
    }
}

extern "C" void kernel_launch(void* const* d_in, const int* in_sizes, int n_in,
                              void* d_out, int out_size) {
    const float* h        = (const float*)d_in[0];
    const int*   tour_raw = (const int*)d_in[1];
    const float* W1m      = (const float*)d_in[2];
    const float* b1m      = (const float*)d_in[3];
    const float* W2m      = (const float*)d_in[4];
    const float* b2m      = (const float*)d_in[5];
    const float* W1u      = (const float*)d_in[6];
    const float* b1u      = (const float*)d_in[7];
    const float* W2u      = (const float*)d_in[8];
    const float* b2u      = (const float*)d_in[9];
    const float* gamma    = (const float*)d_in[10];
    const float* beta     = (const float*)d_in[11];
    float* out            = (float*)d_out;

    __half *A, *C, *P, *wimg;
    int* tour;
    cudaGetSymbolAddress((void**)&A,    g_A);
    cudaGetSymbolAddress((void**)&C,    g_C);
    cudaGetSymbolAddress((void**)&P,    g_P);
    cudaGetSymbolAddress((void**)&wimg, g_wimg);
    cudaGetSymbolAddress((void**)&tour, g_tour);

    cudaFuncSetAttribute(k_mma3,  cudaFuncAttributeMaxDynamicSharedMemorySize, SMEMB);
    cudaFuncSetAttribute(k_chain, cudaFuncAttributeMaxDynamicSharedMemorySize, SMEMB);

    // weight images: 0=W1m0 1=W1m1 2=W2m 3=W1u0 4=W1u1 5=W2u (each 16384 fp16)
    __half* I0 = wimg;
    __half* I1 = wimg + 16384;
    __half* I2 = wimg + 2 * 16384;
    __half* I3 = wimg + 3 * 16384;
    __half* I4 = wimg + 4 * 16384;
    __half* I5 = wimg + 5 * 16384;

    const int G = TOKc / 128;   // 1250 blocks

    k_detect<<<1, 1>>>(tour_raw);
    k_convert<<<(TOKc + 255) / 256, 256>>>(tour_raw, tour);
    k_prepw<<<(6 * 16384 + 255) / 256, 256>>>(W1m, W2m, W1u, W2u, wimg);

    // K_A: A = gather(h)@W1m0, C = @W1m1, P = @W1u0
    k_mma3<<<G, 256, SMEMB>>>(h, tour, I0, I1, I3, A, C, P);
    // K_B: roll -> W2m -> W1u1(silu+P) -> W2u -> LN -> scatter
    k_chain<<<G, 256, SMEMB>>>(A, C, P, h, tour, I2, I4, I5,
                               b1m, b2m, b1u, b2u, gamma, beta, out);
}